// round 7
// baseline (speedup 1.0000x reference)
#include <cuda_runtime.h>

#define NT    256         // threads per CTA
#define VPT   8           // float4 vectors per thread (8*4*256 = 8192)
#define COLS  8192        // row length
#define CAP   2048        // SMEM candidate buffer capacity
#define NBINS 4096        // fine radix bins (12 bits/level)

// Monotone mapping: float -> uint32 such that float order == unsigned order.
__device__ __forceinline__ unsigned mono(float f) {
    unsigned u = __float_as_uint(f);
    return (u & 0x80000000u) ? ~u : (u | 0x80000000u);
}

// Inverse of mono(). Clamps NaN bit patterns (from synthetic bin edges) to +-inf.
__device__ __forceinline__ float inv_mono(unsigned k) {
    unsigned u = (k & 0x80000000u) ? (k & 0x7FFFFFFFu) : ~k;
    if ((u & 0x7F800000u) == 0x7F800000u && (u & 0x007FFFFFu))
        u = (u & 0x80000000u) | 0x7F800000u;
    return __uint_as_float(u);
}

// Single-warp collective: walk a 1024-bin histogram from the TOP bin down, find
// the bin where the cumulative count first reaches rr. All 32 lanes must call.
__device__ __forceinline__ void rank_walk(const unsigned* hist, unsigned rr, int lane,
                                          unsigned& bin_out, unsigned& nr_out) {
    const int base = 1024 - 32 * (lane + 1);   // lane 0 owns the TOP 32 bins
    unsigned s = 0;
#pragma unroll
    for (int i = 0; i < 32; i++) s += hist[base + i];
    unsigned p = s, t;
    t = __shfl_up_sync(0xFFFFFFFFu, p, 1);  if (lane >= 1)  p += t;
    t = __shfl_up_sync(0xFFFFFFFFu, p, 2);  if (lane >= 2)  p += t;
    t = __shfl_up_sync(0xFFFFFFFFu, p, 4);  if (lane >= 4)  p += t;
    t = __shfl_up_sync(0xFFFFFFFFu, p, 8);  if (lane >= 8)  p += t;
    t = __shfl_up_sync(0xFFFFFFFFu, p, 16); if (lane >= 16) p += t;
    const unsigned excl = p - s;
    const bool hit = (excl < rr) && (rr <= p);
    const unsigned m = __ballot_sync(0xFFFFFFFFu, hit);
    unsigned bin = 0, nr = rr;
    if (m) {
        const int hl = __ffs(m) - 1;
        if (lane == hl) {
            unsigned cum = excl;
            for (int b = base + 31; b >= base; b--) {
                cum += hist[b];
                if (cum >= rr) { bin = (unsigned)b; nr = rr - (cum - hist[b]); break; }
            }
        }
        bin = __shfl_sync(0xFFFFFFFFu, bin, hl);
        nr  = __shfl_sync(0xFFFFFFFFu, nr, hl);
    }
    bin_out = bin; nr_out = nr;
}

__global__ void __launch_bounds__(NT, 4) ksparse_kernel(const float* __restrict__ in,
                                                        const int* __restrict__ kp,
                                                        float* __restrict__ out) {
    __shared__ unsigned buf[CAP];        // 8 KB: bracket-relative candidate keys
    __shared__ unsigned hist[NBINS];     // 16 KB (P1/P2 use first 1024 bins)
    __shared__ unsigned chunkscan[128];  // cooperative-walk partials
    __shared__ unsigned warpsum[8];
    __shared__ int s_cnt;
    __shared__ unsigned s_hibin, s_lobin, s_bin, s_rank;
    __shared__ float s_T;

    const int tid  = threadIdx.x;
    const int lane = tid & 31;
    const int wid  = tid >> 5;

    const float4* rp = (const float4*)(in  + (size_t)blockIdx.x * COLS);
    float4*       op = (float4*)      (out + (size_t)blockIdx.x * COLS);

    // Entire row resident in registers: one global read.
    float4 v[VPT];
#pragma unroll
    for (int i = 0; i < VPT; i++) v[i] = rp[tid + i * NT];

    const int K = kp ? __ldg(kp) : 512;
    const unsigned r = (unsigned)(K + 1);   // rank of threshold (descending, 1-indexed)

    hist[tid] = 0; hist[tid + NT] = 0; hist[tid + 2 * NT] = 0; hist[tid + 3 * NT] = 0;
    __syncthreads();

    // ---- Phase 1: sample histogram (4 samples/thread = 1024) ----
    atomicAdd(&hist[mono(v[0].x) >> 22], 1u);
    atomicAdd(&hist[mono(v[0].z) >> 22], 1u);
    atomicAdd(&hist[mono(v[4].x) >> 22], 1u);
    atomicAdd(&hist[mono(v[4].z) >> 22], 1u);
    __syncthreads();

    // ---- Phase 2: bracket pivots — hi walk (warp 0) and lo walk (warp 1) in parallel ----
    {
        const float ex = (float)r * (1024.0f / (float)COLS);   // expected sample rank
        const float sd = sqrtf(ex + 4.0f);
        if (wid == 0) {
            int hi_cut = (int)(ex - 5.0f * sd - 2.0f); if (hi_cut < 0) hi_cut = 0;
            unsigned b, nr;
            rank_walk(hist, (unsigned)hi_cut + 1u, lane, b, nr);
            if (lane == 0) s_hibin = b;
        } else if (wid == 1) {
            int lo_cut = (int)(ex + 5.0f * sd + 8.0f); if (lo_cut > 1024) lo_cut = 1024;
            unsigned b, nr;
            rank_walk(hist, (unsigned)lo_cut, lane, b, nr);
            if (lane == 0) s_lobin = b;
        }
    }
    __syncthreads();
    const unsigned HI_bin = s_hibin, LO_bin = s_lobin;
    const unsigned khi = ((HI_bin + 1u) << 22) - 1u;          // key of U_hi
    const unsigned klo = (LO_bin << 22) - 1u;                 // key of U_lo (LO_bin>0)
    const float U_hi = inv_mono(khi);
    const float U_lo = (LO_bin == 0u) ? __int_as_float(0xFF800000) : inv_mono(klo);

    // ---- Phase 3a: predicate masks over registers (no atomics, no branches) ----
    unsigned mhi = 0, mbr = 0;
#pragma unroll
    for (int i = 0; i < VPT; i++) {
#pragma unroll
        for (int j = 0; j < 4; j++) {
            const float x = (&v[i].x)[j];
            const bool a = x > U_hi;
            const bool b = (x > U_lo) && !a;
            mhi |= ((unsigned)a) << (i * 4 + j);
            mbr |= ((unsigned)b) << (i * 4 + j);
        }
    }
    // Packed block scan: high 16 bits = count(>U_hi), low 16 = bracket count.
    const unsigned packed = ((unsigned)__popc(mhi) << 16) | (unsigned)__popc(mbr);
    unsigned inc = packed, t;
    t = __shfl_up_sync(0xFFFFFFFFu, inc, 1);  if (lane >= 1)  inc += t;
    t = __shfl_up_sync(0xFFFFFFFFu, inc, 2);  if (lane >= 2)  inc += t;
    t = __shfl_up_sync(0xFFFFFFFFu, inc, 4);  if (lane >= 4)  inc += t;
    t = __shfl_up_sync(0xFFFFFFFFu, inc, 8);  if (lane >= 8)  inc += t;
    t = __shfl_up_sync(0xFFFFFFFFu, inc, 16); if (lane >= 16) inc += t;
    if (lane == 31) warpsum[wid] = inc;
    __syncthreads();
    if (wid == 0) {
        unsigned w = (lane < 8) ? warpsum[lane] : 0;
        t = __shfl_up_sync(0xFFFFFFFFu, w, 1); if (lane >= 1) w += t;
        t = __shfl_up_sync(0xFFFFFFFFu, w, 2); if (lane >= 2) w += t;
        t = __shfl_up_sync(0xFFFFFFFFu, w, 4); if (lane >= 4) w += t;
        if (lane < 8) warpsum[lane] = w;
    }
    __syncthreads();
    const unsigned tot  = warpsum[7];
    const unsigned excl = (wid ? warpsum[wid - 1] : 0u) + inc - packed;
    const int CHI  = (int)(tot >> 16);
    const int nbuf = (int)(tot & 0xFFFFu);
    int pos = (int)(excl & 0xFFFFu);

    // ---- Phase 3b: push bracket-relative keys to owned slots ----
#pragma unroll
    for (int i = 0; i < VPT; i++) {
#pragma unroll
        for (int j = 0; j < 4; j++) {
            if ((mbr >> (i * 4 + j)) & 1u) {
                if (pos < CAP) buf[pos] = mono((&v[i].x)[j]) - klo - 1u;
                pos++;
            }
        }
    }
    __syncthreads();

    const int rr0 = (int)r - CHI;
    const unsigned span = khi - klo;               // bracket width in key units
    const bool ok = (LO_bin > 0u) && (span <= (1u << 24)) &&
                    (nbuf <= CAP) && (rr0 >= 1) && (rr0 <= nbuf);

    if (ok) {
        // ---- Phase 4: exact rank-select over 24-bit relative keys, 2 levels x 12 bits ----
        unsigned pfx = 0;
        unsigned rank = (unsigned)rr0;
#pragma unroll
        for (int lvl = 0; lvl < 2; lvl++) {
            // zero 4096-bin hist
#pragma unroll
            for (int k = 0; k < NBINS / NT; k++) hist[tid + k * NT] = 0;
            __syncthreads();
            // sweep
            if (lvl == 0) {
                for (int i = tid; i < nbuf; i += NT)
                    atomicAdd(&hist[buf[i] >> 12], 1u);
            } else {
                for (int i = tid; i < nbuf; i += NT) {
                    const unsigned d = buf[i];
                    if ((d >> 12) == pfx) atomicAdd(&hist[d & 4095u], 1u);
                }
            }
            __syncthreads();
            // cooperative walk, phase A: warps 0-3 build 128 chunk partial scans
            if (wid < 4) {
                const int c = wid * 32 + lane;             // chunk index, 0 = topmost
                const int bbase = NBINS - 32 * (c + 1);
                unsigned s = 0;
#pragma unroll
                for (int i = 0; i < 32; i++) s += hist[bbase + i];
                unsigned p = s, tt;
                tt = __shfl_up_sync(0xFFFFFFFFu, p, 1);  if (lane >= 1)  p += tt;
                tt = __shfl_up_sync(0xFFFFFFFFu, p, 2);  if (lane >= 2)  p += tt;
                tt = __shfl_up_sync(0xFFFFFFFFu, p, 4);  if (lane >= 4)  p += tt;
                tt = __shfl_up_sync(0xFFFFFFFFu, p, 8);  if (lane >= 8)  p += tt;
                tt = __shfl_up_sync(0xFFFFFFFFu, p, 16); if (lane >= 16) p += tt;
                chunkscan[c] = p;                           // warp-local inclusive (top-down)
            }
            __syncthreads();
            // phase B: warp 0 resolves bin + residual rank
            if (wid == 0) {
                const unsigned wt = (lane < 4) ? chunkscan[lane * 32 + 31] : 0u;
                const unsigned w0 = __shfl_sync(0xFFFFFFFFu, wt, 0);
                const unsigned w1 = __shfl_sync(0xFFFFFFFFu, wt, 1);
                const unsigned w2 = __shfl_sync(0xFFFFFFFFu, wt, 2);
                unsigned woff[4]; woff[0] = 0; woff[1] = w0; woff[2] = w0 + w1; woff[3] = w0 + w1 + w2;
                unsigned prevG = 0;
                if (lane > 0) {
                    const int cp = 4 * lane - 1;
                    prevG = woff[cp >> 5] + chunkscan[cp];
                }
                int hitc = -1; unsigned hexcl = 0;
#pragma unroll
                for (int q = 0; q < 4; q++) {
                    const int c = 4 * lane + q;
                    const unsigned G = woff[c >> 5] + chunkscan[c];
                    if (hitc < 0 && prevG < rank && rank <= G) { hitc = c; hexcl = prevG; }
                    prevG = G;
                }
                const unsigned m = __ballot_sync(0xFFFFFFFFu, hitc >= 0);
                unsigned bin = 0, nr = rank;
                if (m) {
                    const int hl = __ffs(m) - 1;
                    if (lane == hl) {
                        const int bbase = NBINS - 32 * (hitc + 1);
                        unsigned cum = hexcl;
                        for (int b = bbase + 31; b >= bbase; b--) {
                            cum += hist[b];
                            if (cum >= rank) { bin = (unsigned)b; nr = rank - (cum - hist[b]); break; }
                        }
                    }
                    bin = __shfl_sync(0xFFFFFFFFu, bin, hl);
                    nr  = __shfl_sync(0xFFFFFFFFu, nr, hl);
                }
                if (lane == 0) { s_bin = bin; s_rank = nr; }
            }
            __syncthreads();
            pfx = (lvl == 0) ? s_bin : ((pfx << 12) | s_bin);
            rank = s_rank;
        }
        if (tid == 0) s_T = inv_mono(klo + 1u + pfx);
    } else {
        // ---- Fallback: exact 32-bit bisection over register data (rare) ----
        unsigned pfx = 0;
        for (int bit = 31; bit >= 0; bit--) {
            const unsigned cand = pfx | (1u << bit);
            int c = 0;
#pragma unroll
            for (int i = 0; i < VPT; i++) {
                c += (mono(v[i].x) >= cand) + (mono(v[i].y) >= cand)
                   + (mono(v[i].z) >= cand) + (mono(v[i].w) >= cand);
            }
#pragma unroll
            for (int off = 16; off; off >>= 1) c += __shfl_down_sync(0xFFFFFFFFu, c, off);
            __syncthreads();
            if (tid == 0) s_cnt = 0;
            __syncthreads();
            if (lane == 0) atomicAdd(&s_cnt, c);
            __syncthreads();
            if ((unsigned)s_cnt >= r) pfx = cand;
        }
        if (tid == 0) s_T = inv_mono(pfx);
    }
    __syncthreads();
    const float T = s_T;

    // ---- Phase 5: mask from registers, single global write ----
#pragma unroll
    for (int i = 0; i < VPT; i++) {
        float4 o;
        o.x = v[i].x > T ? v[i].x : 0.0f;
        o.y = v[i].y > T ? v[i].y : 0.0f;
        o.z = v[i].z > T ? v[i].z : 0.0f;
        o.w = v[i].w > T ? v[i].w : 0.0f;
        op[tid + i * NT] = o;
    }
}

extern "C" void kernel_launch(void* const* d_in, const int* in_sizes, int n_in,
                              void* d_out, int out_size) {
    const float* in = (const float*)d_in[0];
    const int*   kp = (n_in >= 2) ? (const int*)d_in[1] : nullptr;
    float* out = (float*)d_out;
    const int rows = in_sizes[0] / COLS;
    ksparse_kernel<<<rows, NT>>>(in, kp, out);
}

// round 8
// speedup vs baseline: 1.3906x; 1.3906x over previous
#include <cuda_runtime.h>

#define NT   256          // threads per CTA
#define VPT  8            // float4 vectors per thread (8*4*256 = 8192)
#define COLS 8192         // row length
#define CAP  2048         // SMEM candidate buffer capacity
#define GCAP 128          // gather capacity for the hit bin

// Monotone mapping: float -> uint32 such that float order == unsigned order.
__device__ __forceinline__ unsigned mono(float f) {
    unsigned u = __float_as_uint(f);
    return (u & 0x80000000u) ? ~u : (u | 0x80000000u);
}

// Inverse of mono(). Clamps NaN bit patterns (from synthetic bin edges) to +-inf.
__device__ __forceinline__ float inv_mono(unsigned k) {
    unsigned u = (k & 0x80000000u) ? (k & 0x7FFFFFFFu) : ~k;
    if ((u & 0x7F800000u) == 0x7F800000u && (u & 0x007FFFFFu))
        u = (u & 0x80000000u) | 0x7F800000u;
    return __uint_as_float(u);
}

// Single-warp collective: walk a 1024-bin histogram from the TOP bin down, find
// the bin where the cumulative count first reaches rr. All 32 lanes must call.
__device__ __forceinline__ void rank_walk(const unsigned* hist, unsigned rr, int lane,
                                          unsigned& bin_out, unsigned& nr_out) {
    const int base = 1024 - 32 * (lane + 1);   // lane 0 owns the TOP 32 bins
    unsigned s = 0;
#pragma unroll
    for (int i = 0; i < 32; i++) s += hist[base + i];
    unsigned p = s, t;
    t = __shfl_up_sync(0xFFFFFFFFu, p, 1);  if (lane >= 1)  p += t;
    t = __shfl_up_sync(0xFFFFFFFFu, p, 2);  if (lane >= 2)  p += t;
    t = __shfl_up_sync(0xFFFFFFFFu, p, 4);  if (lane >= 4)  p += t;
    t = __shfl_up_sync(0xFFFFFFFFu, p, 8);  if (lane >= 8)  p += t;
    t = __shfl_up_sync(0xFFFFFFFFu, p, 16); if (lane >= 16) p += t;
    const unsigned excl = p - s;
    const bool hit = (excl < rr) && (rr <= p);
    const unsigned m = __ballot_sync(0xFFFFFFFFu, hit);
    unsigned bin = 0, nr = rr;
    if (m) {
        const int hl = __ffs(m) - 1;
        if (lane == hl) {
            unsigned cum = excl;
            for (int b = base + 31; b >= base; b--) {
                cum += hist[b];
                if (cum >= rr) { bin = (unsigned)b; nr = rr - (cum - hist[b]); break; }
            }
        }
        bin = __shfl_sync(0xFFFFFFFFu, bin, hl);
        nr  = __shfl_sync(0xFFFFFFFFu, nr, hl);
    }
    bin_out = bin; nr_out = nr;
}

__global__ void __launch_bounds__(NT, 4) ksparse_kernel(const float* __restrict__ in,
                                                        const int* __restrict__ kp,
                                                        float* __restrict__ out) {
    __shared__ unsigned buf[CAP];      // 8 KB: bracket-relative candidate keys
    __shared__ unsigned hist[1024];    // 4 KB
    __shared__ unsigned g[GCAP];       // hit-bin gather
    __shared__ unsigned warpsum[8];
    __shared__ int s_cnt, s_gn;
    __shared__ unsigned s_hibin, s_lobin, s_bin, s_rank;
    __shared__ float s_T;

    const int tid  = threadIdx.x;
    const int lane = tid & 31;
    const int wid  = tid >> 5;

    const float4* rp = (const float4*)(in  + (size_t)blockIdx.x * COLS);
    float4*       op = (float4*)      (out + (size_t)blockIdx.x * COLS);

    // Entire row resident in registers: one global read.
    float4 v[VPT];
#pragma unroll
    for (int i = 0; i < VPT; i++) v[i] = rp[tid + i * NT];

    const int K = kp ? __ldg(kp) : 512;
    const unsigned r = (unsigned)(K + 1);   // rank of threshold (descending, 1-indexed)

    hist[tid] = 0; hist[tid + NT] = 0; hist[tid + 2 * NT] = 0; hist[tid + 3 * NT] = 0;
    if (tid == 0) s_gn = 0;
    __syncthreads();

    // ---- Phase 1: sample histogram (2 samples/thread = 512) ----
    atomicAdd(&hist[mono(v[0].x) >> 22], 1u);
    atomicAdd(&hist[mono(v[4].x) >> 22], 1u);
    __syncthreads();

    // ---- Phase 2: bracket pivots — hi walk (warp 0) and lo walk (warp 1) parallel ----
    {
        const float ex = (float)r * (512.0f / (float)COLS);   // expected sample rank
        const float sd = sqrtf(ex + 4.0f);
        if (wid == 0) {
            int hi_cut = (int)(ex - 5.0f * sd - 2.0f); if (hi_cut < 0) hi_cut = 0;
            unsigned b, nr;
            rank_walk(hist, (unsigned)hi_cut + 1u, lane, b, nr);
            if (lane == 0) s_hibin = b;
        } else if (wid == 1) {
            int lo_cut = (int)(ex + 5.0f * sd + 8.0f); if (lo_cut > 512) lo_cut = 512;
            unsigned b, nr;
            rank_walk(hist, (unsigned)lo_cut, lane, b, nr);
            if (lane == 0) s_lobin = b;
        }
    }
    __syncthreads();
    const unsigned HI_bin = s_hibin, LO_bin = s_lobin;
    const unsigned khi = ((HI_bin + 1u) << 22) - 1u;          // key of U_hi
    const unsigned klo = (LO_bin << 22) - 1u;                 // key of U_lo (LO_bin>0)
    const float U_hi = inv_mono(khi);
    const float U_lo = (LO_bin == 0u) ? __int_as_float(0xFF800000) : inv_mono(klo);

    // ---- Phase 3a: predicate masks over registers (no atomics, no branches) ----
    unsigned mhi = 0, mbr = 0;
#pragma unroll
    for (int i = 0; i < VPT; i++) {
#pragma unroll
        for (int j = 0; j < 4; j++) {
            const float x = (&v[i].x)[j];
            const bool a = x > U_hi;
            const bool b = (x > U_lo) && !a;
            mhi |= ((unsigned)a) << (i * 4 + j);
            mbr |= ((unsigned)b) << (i * 4 + j);
        }
    }
    // Packed block scan: high 16 bits = count(>U_hi), low 16 = bracket count.
    const unsigned packed = ((unsigned)__popc(mhi) << 16) | (unsigned)__popc(mbr);
    unsigned inc = packed, t;
    t = __shfl_up_sync(0xFFFFFFFFu, inc, 1);  if (lane >= 1)  inc += t;
    t = __shfl_up_sync(0xFFFFFFFFu, inc, 2);  if (lane >= 2)  inc += t;
    t = __shfl_up_sync(0xFFFFFFFFu, inc, 4);  if (lane >= 4)  inc += t;
    t = __shfl_up_sync(0xFFFFFFFFu, inc, 8);  if (lane >= 8)  inc += t;
    t = __shfl_up_sync(0xFFFFFFFFu, inc, 16); if (lane >= 16) inc += t;
    if (lane == 31) warpsum[wid] = inc;
    __syncthreads();
    if (wid == 0) {
        unsigned w = (lane < 8) ? warpsum[lane] : 0;
        t = __shfl_up_sync(0xFFFFFFFFu, w, 1); if (lane >= 1) w += t;
        t = __shfl_up_sync(0xFFFFFFFFu, w, 2); if (lane >= 2) w += t;
        t = __shfl_up_sync(0xFFFFFFFFu, w, 4); if (lane >= 4) w += t;
        if (lane < 8) warpsum[lane] = w;
    }
    __syncthreads();
    const unsigned tot  = warpsum[7];
    const unsigned excl = (wid ? warpsum[wid - 1] : 0u) + inc - packed;
    const int CHI  = (int)(tot >> 16);
    const int nbuf = (int)(tot & 0xFFFFu);
    int pos = (int)(excl & 0xFFFFu);

    // ---- Phase 3b: push bracket-relative keys to owned slots ----
#pragma unroll
    for (int i = 0; i < VPT; i++) {
#pragma unroll
        for (int j = 0; j < 4; j++) {
            if ((mbr >> (i * 4 + j)) & 1u) {
                if (pos < CAP) buf[pos] = mono((&v[i].x)[j]) - klo - 1u;
                pos++;
            }
        }
    }
    __syncthreads();

    const int rr0 = (int)r - CHI;
    const unsigned span = khi - klo;               // bracket width in key units
    const bool ok = (LO_bin > 0u) && (span <= (1u << 24)) &&
                    (nbuf <= CAP) && (rr0 >= 1) && (rr0 <= nbuf);
    bool need_fb = !ok;                            // block-uniform

    if (ok) {
        // ---- Phase 4a: one 10-bit level over bracket-relative keys ----
        hist[tid] = 0; hist[tid + NT] = 0; hist[tid + 2 * NT] = 0; hist[tid + 3 * NT] = 0;
        __syncthreads();
        for (int i = tid; i < nbuf; i += NT)
            atomicAdd(&hist[buf[i] >> 14], 1u);
        __syncthreads();
        if (wid == 0) {
            unsigned b, nr;
            rank_walk(hist, (unsigned)rr0, lane, b, nr);
            if (lane == 0) { s_bin = b; s_rank = nr; }
        }
        __syncthreads();
        const unsigned bin = s_bin;
        const unsigned nr  = s_rank;
        const int m = (int)hist[bin];
        if (m <= GCAP) {
            // ---- Phase 4b: gather hit-bin keys ----
            for (int i = tid; i < nbuf; i += NT) {
                const unsigned d = buf[i];
                if ((d >> 14) == bin) {
                    const int p = atomicAdd(&s_gn, 1);
                    if (p < GCAP) g[p] = d;
                }
            }
            __syncthreads();
            // ---- Phase 4c: warp 0 selects the nr-th largest among m keys ----
            if (wid == 0) {
                unsigned my[4]; int gt[4] = {0,0,0,0}, ge[4] = {0,0,0,0};
#pragma unroll
                for (int q = 0; q < 4; q++)
                    my[q] = (lane + 32 * q < m) ? g[lane + 32 * q] : 0u;
                for (int i = 0; i < m; i++) {
                    const unsigned ki = g[i];
#pragma unroll
                    for (int q = 0; q < 4; q++) {
                        gt[q] += (ki > my[q]);
                        ge[q] += (ki >= my[q]);
                    }
                }
                bool found = false; unsigned sel = 0;
#pragma unroll
                for (int q = 0; q < 4; q++) {
                    const bool hit = (lane + 32 * q < m) &&
                                     ((unsigned)gt[q] < nr) && (nr <= (unsigned)ge[q]);
                    if (hit && !found) { sel = my[q]; found = true; }
                }
                const unsigned bm = __ballot_sync(0xFFFFFFFFu, found);
                if (bm && lane == __ffs(bm) - 1) s_T = inv_mono(klo + 1u + sel);
            }
        } else {
            need_fb = true;                        // block-uniform (m from SMEM)
        }
    }
    __syncthreads();

    if (need_fb) {
        // ---- Fallback: exact 32-bit bisection over register data (rare) ----
        unsigned pfx = 0;
        for (int bit = 31; bit >= 0; bit--) {
            const unsigned cand = pfx | (1u << bit);
            int c = 0;
#pragma unroll
            for (int i = 0; i < VPT; i++) {
                c += (mono(v[i].x) >= cand) + (mono(v[i].y) >= cand)
                   + (mono(v[i].z) >= cand) + (mono(v[i].w) >= cand);
            }
#pragma unroll
            for (int off = 16; off; off >>= 1) c += __shfl_down_sync(0xFFFFFFFFu, c, off);
            __syncthreads();
            if (tid == 0) s_cnt = 0;
            __syncthreads();
            if (lane == 0) atomicAdd(&s_cnt, c);
            __syncthreads();
            if ((unsigned)s_cnt >= r) pfx = cand;
        }
        if (tid == 0) s_T = inv_mono(pfx);
        __syncthreads();
    }
    const float T = s_T;

    // ---- Phase 5: mask from registers, single global write ----
#pragma unroll
    for (int i = 0; i < VPT; i++) {
        float4 o;
        o.x = v[i].x > T ? v[i].x : 0.0f;
        o.y = v[i].y > T ? v[i].y : 0.0f;
        o.z = v[i].z > T ? v[i].z : 0.0f;
        o.w = v[i].w > T ? v[i].w : 0.0f;
        op[tid + i * NT] = o;
    }
}

extern "C" void kernel_launch(void* const* d_in, const int* in_sizes, int n_in,
                              void* d_out, int out_size) {
    const float* in = (const float*)d_in[0];
    const int*   kp = (n_in >= 2) ? (const int*)d_in[1] : nullptr;
    float* out = (float*)d_out;
    const int rows = in_sizes[0] / COLS;
    ksparse_kernel<<<rows, NT>>>(in, kp, out);
}